// round 1
// baseline (speedup 1.0000x reference)
#include <cuda_runtime.h>
#include <math.h>

#define DM 1024
#define SEQ 2048
#define BT 2
#define NH 16
#define DK 64
#define ROWS (BT*SEQ)      /* 4096 */
#define BHCNT (BT*NH)      /* 32   */

// -------- scratch (device globals; no runtime allocation) --------
static __device__ float g_hn[(size_t)ROWS * DM];
static __device__ float g_q[(size_t)BHCNT * SEQ * DK];
static __device__ float g_k[(size_t)BHCNT * SEQ * DK];
static __device__ float g_v[(size_t)BHCNT * SEQ * DK];
static __device__ float g_o[(size_t)ROWS * DM];

// ============================================================
// LayerNorm: one block per row, 256 threads, 4 floats/thread
// ============================================================
__global__ void __launch_bounds__(256) ln_kernel(const float* __restrict__ h,
                                                 const float* __restrict__ w,
                                                 const float* __restrict__ b)
{
    const int row = blockIdx.x;
    const int t = threadIdx.x;
    const float4* x4 = reinterpret_cast<const float4*>(h) + (size_t)row * (DM / 4);
    float4 v = x4[t];
    float s  = v.x + v.y + v.z + v.w;
    float sq = v.x*v.x + v.y*v.y + v.z*v.z + v.w*v.w;
    #pragma unroll
    for (int o = 16; o > 0; o >>= 1) {
        s  += __shfl_xor_sync(0xffffffffu, s,  o);
        sq += __shfl_xor_sync(0xffffffffu, sq, o);
    }
    __shared__ float sh[16];
    __shared__ float mu_s, rs_s;
    const int wid = t >> 5;
    if ((t & 31) == 0) { sh[wid] = s; sh[8 + wid] = sq; }
    __syncthreads();
    if (t == 0) {
        float S = 0.f, Q = 0.f;
        #pragma unroll
        for (int i = 0; i < 8; i++) { S += sh[i]; Q += sh[8 + i]; }
        float mu  = S * (1.0f / DM);
        float var = Q * (1.0f / DM) - mu * mu;
        mu_s = mu;
        rs_s = rsqrtf(var + 1e-5f);
    }
    __syncthreads();
    const float mu = mu_s, rs = rs_s;
    float4 wv = reinterpret_cast<const float4*>(w)[t];
    float4 bv = reinterpret_cast<const float4*>(b)[t];
    float4 o4;
    o4.x = (v.x - mu) * rs * wv.x + bv.x;
    o4.y = (v.y - mu) * rs * wv.y + bv.y;
    o4.z = (v.z - mu) * rs * wv.z + bv.z;
    o4.w = (v.w - mu) * rs * wv.w + bv.w;
    reinterpret_cast<float4*>(g_hn)[(size_t)row * (DM / 4) + t] = o4;
}

// ============================================================
// QKV GEMM: y = hn @ W^T + b, scattered into [b,h,s,d] layout.
// 64x64 tile, BK=16, 256 threads, 4x4 microtile.
// blockIdx.z selects Q/K/V.
// ============================================================
__global__ void __launch_bounds__(256) qkv_gemm(
    const float* __restrict__ Wq, const float* __restrict__ bq,
    const float* __restrict__ Wk, const float* __restrict__ bk,
    const float* __restrict__ Wv, const float* __restrict__ bv)
{
    const float* W; const float* bias; float* out;
    if (blockIdx.z == 0)      { W = Wq; bias = bq; out = g_q; }
    else if (blockIdx.z == 1) { W = Wk; bias = bk; out = g_k; }
    else                      { W = Wv; bias = bv; out = g_v; }

    __shared__ float As[64][20];
    __shared__ float WsT[16][68];

    const int tid = threadIdx.x;
    const int tx = tid & 15, ty = tid >> 4;
    const int lr = tid >> 2, lc = tid & 3;
    const int m0 = blockIdx.y * 64, n0 = blockIdx.x * 64;

    float acc[4][4] = {};

    const float* Arow = g_hn + (size_t)(m0 + lr) * DM + 4 * lc;
    const float* Wrow = W    + (size_t)(n0 + lr) * DM + 4 * lc;

    for (int k0 = 0; k0 < DM; k0 += 16) {
        float4 av = *reinterpret_cast<const float4*>(Arow + k0);
        float4 wv = *reinterpret_cast<const float4*>(Wrow + k0);
        *reinterpret_cast<float4*>(&As[lr][4 * lc]) = av;
        WsT[4 * lc + 0][lr] = wv.x;
        WsT[4 * lc + 1][lr] = wv.y;
        WsT[4 * lc + 2][lr] = wv.z;
        WsT[4 * lc + 3][lr] = wv.w;
        __syncthreads();
        #pragma unroll
        for (int kk = 0; kk < 16; kk++) {
            float4 bv4 = *reinterpret_cast<const float4*>(&WsT[kk][4 * tx]);
            #pragma unroll
            for (int r = 0; r < 4; r++) {
                float a = As[4 * ty + r][kk];
                acc[r][0] += a * bv4.x;
                acc[r][1] += a * bv4.y;
                acc[r][2] += a * bv4.z;
                acc[r][3] += a * bv4.w;
            }
        }
        __syncthreads();
    }

    const int head = n0 >> 6;   // 64-wide n tile == one head
    #pragma unroll
    for (int r = 0; r < 4; r++) {
        int m = m0 + 4 * ty + r;
        int batch = m >> 11, srow = m & (SEQ - 1);
        float* orow = out + (((size_t)(batch * NH + head)) * SEQ + srow) * DK + 4 * tx;
        #pragma unroll
        for (int c = 0; c < 4; c++)
            orow[c] = acc[r][c] + bias[n0 + 4 * tx + c];
    }
}

// ============================================================
// Flash-style attention: block = 64 query rows of one (b,h).
// Streams K/V tiles of 64 rows; online softmax; no score matrix
// ever hits HBM.
// ============================================================
#define ATTN_SMEM ((3 * 64 * 68 + 64 * 64) * 4)

__global__ void __launch_bounds__(256) attn_kernel()
{
    extern __shared__ float sm[];
    float (*Qs)[68]  = reinterpret_cast<float (*)[68]>(sm);                 // [i][d]
    float (*KsT)[68] = reinterpret_cast<float (*)[68]>(sm + 64 * 68);       // [d][j]
    float (*Ps)[68]  = reinterpret_cast<float (*)[68]>(sm + 2 * 64 * 68);   // [i][j]
    float (*Vs)[64]  = reinterpret_cast<float (*)[64]>(sm + 3 * 64 * 68);   // [j][d]

    const int tid = threadIdx.x;
    const int tx = tid & 15, ty = tid >> 4;
    const int qt = blockIdx.x, bh = blockIdx.y;

    const float4* Qg = reinterpret_cast<const float4*>(g_q) + (size_t)bh * SEQ * (DK / 4);
    const float4* Kg = reinterpret_cast<const float4*>(g_k) + (size_t)bh * SEQ * (DK / 4);
    const float4* Vg = reinterpret_cast<const float4*>(g_v) + (size_t)bh * SEQ * (DK / 4);

    // load Q tile (natural [i][d], padded rows)
    #pragma unroll
    for (int l = 0; l < 4; l++) {
        int fid = l * 256 + tid;
        int rr = fid >> 4, c4 = fid & 15;
        float4 qv = Qg[(size_t)(qt * 64 + rr) * 16 + c4];
        *reinterpret_cast<float4*>(&Qs[rr][4 * c4]) = qv;
    }

    float m_r[4], l_r[4], o[4][4];
    #pragma unroll
    for (int r = 0; r < 4; r++) {
        m_r[r] = -3.0e38f; l_r[r] = 0.f;
        #pragma unroll
        for (int c = 0; c < 4; c++) o[r][c] = 0.f;
    }
    const float scale = 0.125f;   // 1/sqrt(64)

    for (int kt = 0; kt < SEQ / 64; kt++) {
        // load K transposed (conflict-free LDS.128 on depth loop) + V natural
        #pragma unroll
        for (int l = 0; l < 4; l++) {
            int fid = l * 256 + tid;
            int rr = fid >> 4, c4 = fid & 15;
            float4 kv = Kg[(size_t)(kt * 64 + rr) * 16 + c4];
            KsT[4 * c4 + 0][rr] = kv.x;
            KsT[4 * c4 + 1][rr] = kv.y;
            KsT[4 * c4 + 2][rr] = kv.z;
            KsT[4 * c4 + 3][rr] = kv.w;
            float4 vv = Vg[(size_t)(kt * 64 + rr) * 16 + c4];
            *reinterpret_cast<float4*>(&Vs[rr][4 * c4]) = vv;
        }
        __syncthreads();

        // S = Q K^T (each thread 4x4 of the 64x64 tile)
        float s[4][4] = {};
        #pragma unroll 8
        for (int d = 0; d < DK; d++) {
            float4 bv4 = *reinterpret_cast<const float4*>(&KsT[d][4 * tx]);
            #pragma unroll
            for (int r = 0; r < 4; r++) {
                float a = Qs[4 * ty + r][d];
                s[r][0] += a * bv4.x;
                s[r][1] += a * bv4.y;
                s[r][2] += a * bv4.z;
                s[r][3] += a * bv4.w;
            }
        }

        // online softmax (row stats replicated across the 16 tx lanes)
        #pragma unroll
        for (int r = 0; r < 4; r++) {
            s[r][0] *= scale; s[r][1] *= scale; s[r][2] *= scale; s[r][3] *= scale;
            float rm = fmaxf(fmaxf(s[r][0], s[r][1]), fmaxf(s[r][2], s[r][3]));
            #pragma unroll
            for (int off = 8; off > 0; off >>= 1)
                rm = fmaxf(rm, __shfl_xor_sync(0xffffffffu, rm, off));
            float mn = fmaxf(m_r[r], rm);
            float corr = __expf(m_r[r] - mn);
            m_r[r] = mn;
            float p0 = __expf(s[r][0] - mn);
            float p1 = __expf(s[r][1] - mn);
            float p2 = __expf(s[r][2] - mn);
            float p3 = __expf(s[r][3] - mn);
            float rsum = p0 + p1 + p2 + p3;
            #pragma unroll
            for (int off = 8; off > 0; off >>= 1)
                rsum += __shfl_xor_sync(0xffffffffu, rsum, off);
            l_r[r] = l_r[r] * corr + rsum;
            o[r][0] *= corr; o[r][1] *= corr; o[r][2] *= corr; o[r][3] *= corr;
            *reinterpret_cast<float4*>(&Ps[4 * ty + r][4 * tx]) = make_float4(p0, p1, p2, p3);
        }
        __syncthreads();

        // O += P V
        #pragma unroll 8
        for (int j = 0; j < 64; j++) {
            float4 bv4 = *reinterpret_cast<const float4*>(&Vs[j][4 * tx]);
            #pragma unroll
            for (int r = 0; r < 4; r++) {
                float a = Ps[4 * ty + r][j];
                o[r][0] += a * bv4.x;
                o[r][1] += a * bv4.y;
                o[r][2] += a * bv4.z;
                o[r][3] += a * bv4.w;
            }
        }
        __syncthreads();
    }

    // normalize + scatter to [b, s, h*64+d]
    const int batch = bh >> 4, head = bh & 15;
    #pragma unroll
    for (int r = 0; r < 4; r++) {
        float inv = 1.0f / l_r[r];
        int srow = qt * 64 + 4 * ty + r;
        float4 ov = make_float4(o[r][0] * inv, o[r][1] * inv, o[r][2] * inv, o[r][3] * inv);
        *reinterpret_cast<float4*>(g_o + ((size_t)(batch * SEQ + srow)) * DM
                                   + head * DK + 4 * tx) = ov;
    }
}

// ============================================================
// Output GEMM: out = o @ Wo^T + bo + h_res
// ============================================================
__global__ void __launch_bounds__(256) out_gemm(
    const float* __restrict__ W, const float* __restrict__ bias,
    const float* __restrict__ hres, float* __restrict__ out)
{
    __shared__ float As[64][20];
    __shared__ float WsT[16][68];

    const int tid = threadIdx.x;
    const int tx = tid & 15, ty = tid >> 4;
    const int lr = tid >> 2, lc = tid & 3;
    const int m0 = blockIdx.y * 64, n0 = blockIdx.x * 64;

    float acc[4][4] = {};

    const float* Arow = g_o + (size_t)(m0 + lr) * DM + 4 * lc;
    const float* Wrow = W   + (size_t)(n0 + lr) * DM + 4 * lc;

    for (int k0 = 0; k0 < DM; k0 += 16) {
        float4 av = *reinterpret_cast<const float4*>(Arow + k0);
        float4 wv = *reinterpret_cast<const float4*>(Wrow + k0);
        *reinterpret_cast<float4*>(&As[lr][4 * lc]) = av;
        WsT[4 * lc + 0][lr] = wv.x;
        WsT[4 * lc + 1][lr] = wv.y;
        WsT[4 * lc + 2][lr] = wv.z;
        WsT[4 * lc + 3][lr] = wv.w;
        __syncthreads();
        #pragma unroll
        for (int kk = 0; kk < 16; kk++) {
            float4 bv4 = *reinterpret_cast<const float4*>(&WsT[kk][4 * tx]);
            #pragma unroll
            for (int r = 0; r < 4; r++) {
                float a = As[4 * ty + r][kk];
                acc[r][0] += a * bv4.x;
                acc[r][1] += a * bv4.y;
                acc[r][2] += a * bv4.z;
                acc[r][3] += a * bv4.w;
            }
        }
        __syncthreads();
    }

    #pragma unroll
    for (int r = 0; r < 4; r++) {
        int m = m0 + 4 * ty + r;
        const float* hr = hres + (size_t)m * DM + n0 + 4 * tx;
        float* orow = out + (size_t)m * DM + n0 + 4 * tx;
        #pragma unroll
        for (int c = 0; c < 4; c++)
            orow[c] = acc[r][c] + bias[n0 + 4 * tx + c] + hr[c];
    }
}

// ============================================================
extern "C" void kernel_launch(void* const* d_in, const int* in_sizes, int n_in,
                              void* d_out, int out_size)
{
    const float* h  = (const float*)d_in[0];
    const float* Wq = (const float*)d_in[1];
    const float* bq = (const float*)d_in[2];
    const float* Wk = (const float*)d_in[3];
    const float* bk = (const float*)d_in[4];
    const float* Wv = (const float*)d_in[5];
    const float* bv = (const float*)d_in[6];
    const float* Wo = (const float*)d_in[7];
    const float* bo = (const float*)d_in[8];
    const float* lw = (const float*)d_in[9];
    const float* lb = (const float*)d_in[10];
    float* out = (float*)d_out;

    // persistent per-function attribute; set before first launch (also runs
    // harmlessly as a no-op during graph capture — not a stream operation)
    cudaFuncSetAttribute(attn_kernel, cudaFuncAttributeMaxDynamicSharedMemorySize, ATTN_SMEM);

    ln_kernel<<<ROWS, 256>>>(h, lw, lb);
    qkv_gemm<<<dim3(DM / 64, ROWS / 64, 3), 256>>>(Wq, bq, Wk, bk, Wv, bv);
    attn_kernel<<<dim3(SEQ / 64, BHCNT), 256, ATTN_SMEM>>>();
    out_gemm<<<dim3(DM / 64, ROWS / 64), 256>>>(Wo, bo, h, out);
}

// round 4
// speedup vs baseline: 2.4772x; 2.4772x over previous
#include <cuda_runtime.h>
#include <cuda_bf16.h>
#include <math.h>
#include <stdint.h>

#define DM 1024
#define SEQ 2048
#define BT 2
#define NH 16
#define DK 64
#define ROWS (BT*SEQ)      /* 4096 */
#define BHCNT (BT*NH)      /* 32   */

typedef unsigned short ushort_t;

// -------- scratch (device globals; no runtime allocation) --------
static __device__ __align__(16) __nv_bfloat16 g_hn_hi[(size_t)ROWS * DM];
static __device__ __align__(16) __nv_bfloat16 g_hn_lo[(size_t)ROWS * DM];
static __device__ __align__(16) __nv_bfloat16 g_w_hi[(size_t)4 * DM * DM];
static __device__ __align__(16) __nv_bfloat16 g_w_lo[(size_t)4 * DM * DM];
static __device__ __align__(16) __nv_bfloat16 g_q_hi[(size_t)BHCNT * SEQ * DK];
static __device__ __align__(16) __nv_bfloat16 g_q_lo[(size_t)BHCNT * SEQ * DK];
static __device__ __align__(16) __nv_bfloat16 g_k_hi[(size_t)BHCNT * SEQ * DK];
static __device__ __align__(16) __nv_bfloat16 g_k_lo[(size_t)BHCNT * SEQ * DK];
static __device__ __align__(16) __nv_bfloat16 g_v_hi[(size_t)BHCNT * SEQ * DK];
static __device__ __align__(16) __nv_bfloat16 g_v_lo[(size_t)BHCNT * SEQ * DK];
static __device__ __align__(16) __nv_bfloat16 g_vt_hi[(size_t)BHCNT * DK * SEQ];
static __device__ __align__(16) __nv_bfloat16 g_vt_lo[(size_t)BHCNT * DK * SEQ];
static __device__ __align__(16) __nv_bfloat16 g_o_hi[(size_t)ROWS * DM];
static __device__ __align__(16) __nv_bfloat16 g_o_lo[(size_t)ROWS * DM];

// ============================================================
// helpers
// ============================================================
__device__ __forceinline__ uint32_t smem_u32(const void* p) {
    uint32_t a;
    asm("{ .reg .u64 t; cvta.to.shared.u64 t, %1; cvt.u32.u64 %0, t; }"
        : "=r"(a) : "l"(p));
    return a;
}

#define CP16(dst, src) \
    asm volatile("cp.async.cg.shared.global [%0], [%1], 16;" :: "r"(dst), "l"(src))
#define CP_COMMIT() asm volatile("cp.async.commit_group;" ::: "memory")
#define CP_WAIT0()  asm volatile("cp.async.wait_group 0;" ::: "memory")
#define CP_WAIT1()  asm volatile("cp.async.wait_group 1;" ::: "memory")

// D += A * B  (m16n8k16, bf16 in, fp32 accum)
__device__ __forceinline__ void mma4(float* d, const uint32_t* a,
                                     uint32_t b0, uint32_t b1) {
    asm volatile("mma.sync.aligned.m16n8k16.row.col.f32.bf16.bf16.f32 "
        "{%0,%1,%2,%3}, {%4,%5,%6,%7}, {%8,%9}, {%0,%1,%2,%3};"
        : "+f"(d[0]), "+f"(d[1]), "+f"(d[2]), "+f"(d[3])
        : "r"(a[0]), "r"(a[1]), "r"(a[2]), "r"(a[3]), "r"(b0), "r"(b1));
}

// split two fp32 -> packed bf16x2 hi + packed bf16x2 lo (x in low half)
__device__ __forceinline__ void split2(float x, float y, uint32_t& h, uint32_t& l) {
    __nv_bfloat16 xh = __float2bfloat16_rn(x);
    __nv_bfloat16 yh = __float2bfloat16_rn(y);
    __nv_bfloat16 xl = __float2bfloat16_rn(x - __bfloat162float(xh));
    __nv_bfloat16 yl = __float2bfloat16_rn(y - __bfloat162float(yh));
    __nv_bfloat162 H(xh, yh), L(xl, yl);
    h = *reinterpret_cast<uint32_t*>(&H);
    l = *reinterpret_cast<uint32_t*>(&L);
}

// multiply both bf16 halves by 0.125 (exact: power of two)
__device__ __forceinline__ uint32_t scale8(uint32_t w) {
    __nv_bfloat162 t = *reinterpret_cast<__nv_bfloat162*>(&w);
    float2 f = __bfloat1622float2(t);
    __nv_bfloat162 r = __floats2bfloat162_rn(f.x * 0.125f, f.y * 0.125f);
    return *reinterpret_cast<uint32_t*>(&r);
}

// ============================================================
// LayerNorm -> bf16 hi/lo row-major
// ============================================================
__global__ void __launch_bounds__(256) ln_kernel(const float* __restrict__ h,
                                                 const float* __restrict__ w,
                                                 const float* __restrict__ b)
{
    const int row = blockIdx.x;
    const int t = threadIdx.x;
    const float4* x4 = reinterpret_cast<const float4*>(h) + (size_t)row * (DM / 4);
    float4 v = x4[t];
    float s  = v.x + v.y + v.z + v.w;
    float sq = v.x*v.x + v.y*v.y + v.z*v.z + v.w*v.w;
    #pragma unroll
    for (int o = 16; o > 0; o >>= 1) {
        s  += __shfl_xor_sync(0xffffffffu, s,  o);
        sq += __shfl_xor_sync(0xffffffffu, sq, o);
    }
    __shared__ float sh[16];
    __shared__ float mu_s, rs_s;
    const int wid = t >> 5;
    if ((t & 31) == 0) { sh[wid] = s; sh[8 + wid] = sq; }
    __syncthreads();
    if (t == 0) {
        float S = 0.f, Q = 0.f;
        #pragma unroll
        for (int i = 0; i < 8; i++) { S += sh[i]; Q += sh[8 + i]; }
        float mu  = S * (1.0f / DM);
        float var = Q * (1.0f / DM) - mu * mu;
        mu_s = mu;
        rs_s = rsqrtf(var + 1e-5f);
    }
    __syncthreads();
    const float mu = mu_s, rs = rs_s;
    float4 wv = reinterpret_cast<const float4*>(w)[t];
    float4 bv = reinterpret_cast<const float4*>(b)[t];
    float o0 = (v.x - mu) * rs * wv.x + bv.x;
    float o1 = (v.y - mu) * rs * wv.y + bv.y;
    float o2 = (v.z - mu) * rs * wv.z + bv.z;
    float o3 = (v.w - mu) * rs * wv.w + bv.w;

    uint32_t h01, l01, h23, l23;
    split2(o0, o1, h01, l01);
    split2(o2, o3, h23, l23);
    size_t e = (size_t)row * DM + 4 * t;
    *reinterpret_cast<uint2*>((ushort_t*)g_hn_hi + e) = make_uint2(h01, h23);
    *reinterpret_cast<uint2*>((ushort_t*)g_hn_lo + e) = make_uint2(l01, l23);
}

// ============================================================
// Weight conversion: fp32 [n][k] -> bf16 hi/lo row-major
// ============================================================
__global__ void __launch_bounds__(256) wconv_kernel(
    const float* __restrict__ Wq, const float* __restrict__ Wk,
    const float* __restrict__ Wv, const float* __restrict__ Wo)
{
    const int wsel = blockIdx.y;
    const float* W = (wsel == 0) ? Wq : (wsel == 1) ? Wk : (wsel == 2) ? Wv : Wo;
    const int n = blockIdx.x;
    const int t = threadIdx.x;
    float4 v = *reinterpret_cast<const float4*>(W + (size_t)n * DM + 4 * t);
    uint32_t h01, l01, h23, l23;
    split2(v.x, v.y, h01, l01);
    split2(v.z, v.w, h23, l23);
    size_t e = (size_t)wsel * DM * DM + (size_t)n * DM + 4 * t;
    *reinterpret_cast<uint2*>((ushort_t*)g_w_hi + e) = make_uint2(h01, h23);
    *reinterpret_cast<uint2*>((ushort_t*)g_w_lo + e) = make_uint2(l01, l23);
}

// ============================================================
// HMMA split-bf16 GEMM: C[128x128] = A[128xK] * W[128xK]^T (+bias...)
// 8 warps, warp tile 64x32, BK=32, double-buffered cp.async.
// smem row pad: 40 bf16 (20 words) -> conflict-free fragment loads.
// ============================================================
#define GMAT_W   2560                 /* words per 128x40 bf16 matrix */
#define GSTAGE_W (4 * GMAT_W)         /* Ahi Alo Bhi Blo */
#define GEMM_SMEM (2 * GSTAGE_W * 4)  /* bytes = 80KB */

__global__ void __launch_bounds__(256, 1) gemm_hmma(
    int mode_base,
    const float* __restrict__ bq, const float* __restrict__ bk,
    const float* __restrict__ bv, const float* __restrict__ bo,
    const float* __restrict__ hres, float* __restrict__ out)
{
    extern __shared__ __align__(16) uint32_t gsm[];
    const int tid = threadIdx.x, lane = tid & 31, wid = tid >> 5;
    const int gid = lane >> 2, tig = lane & 3;
    const int wm = wid & 1, wn = wid >> 1;
    const int mode = mode_base + blockIdx.z;
    const int m0 = blockIdx.y * 128, n0 = blockIdx.x * 128;

    const ushort_t* Agh = (const ushort_t*)((mode < 3) ? g_hn_hi : g_o_hi);
    const ushort_t* Agl = (const ushort_t*)((mode < 3) ? g_hn_lo : g_o_lo);
    const int ws = (mode < 3) ? mode : 3;
    const ushort_t* Bgh = (const ushort_t*)g_w_hi + (size_t)ws * DM * DM;
    const ushort_t* Bgl = (const ushort_t*)g_w_lo + (size_t)ws * DM * DM;

    const uint32_t sb = smem_u32(gsm);

    auto load_stage = [&](int s, int i) {
        #pragma unroll
        for (int half = 0; half < 2; half++) {
            int row = (tid >> 2) + 64 * half;
            int ch = tid & 3;
            size_t gA = (size_t)(m0 + row) * DM + i * 32 + ch * 8;
            size_t gB = (size_t)(n0 + row) * DM + i * 32 + ch * 8;
            uint32_t ds = sb + (s * GSTAGE_W + row * 20 + ch * 4) * 4;
            CP16(ds,                Agh + gA);
            CP16(ds + GMAT_W * 4,   Agl + gA);
            CP16(ds + 2*GMAT_W*4,   Bgh + gB);
            CP16(ds + 3*GMAT_W*4,   Bgl + gB);
        }
    };

    float acc[4][4][4] = {};

    load_stage(0, 0);
    CP_COMMIT();

    for (int i = 0; i < DM / 32; i++) {
        if (i + 1 < DM / 32) {
            load_stage((i + 1) & 1, i + 1);
            CP_COMMIT();
            CP_WAIT1();
        } else {
            CP_WAIT0();
        }
        __syncthreads();

        const uint32_t* Wp = gsm + (i & 1) * GSTAGE_W;
        const uint32_t* Ah = Wp;
        const uint32_t* Al = Wp + GMAT_W;
        const uint32_t* Bh = Wp + 2 * GMAT_W;
        const uint32_t* Bl = Wp + 3 * GMAT_W;

        #pragma unroll
        for (int ks = 0; ks < 2; ks++) {
            const int kw = ks * 8 + tig;
            uint32_t ah[4][4], al[4][4];
            #pragma unroll
            for (int mt = 0; mt < 4; mt++) {
                int r = wm * 64 + mt * 16 + gid;
                ah[mt][0] = Ah[r * 20 + kw];
                ah[mt][1] = Ah[(r + 8) * 20 + kw];
                ah[mt][2] = Ah[r * 20 + kw + 4];
                ah[mt][3] = Ah[(r + 8) * 20 + kw + 4];
                al[mt][0] = Al[r * 20 + kw];
                al[mt][1] = Al[(r + 8) * 20 + kw];
                al[mt][2] = Al[r * 20 + kw + 4];
                al[mt][3] = Al[(r + 8) * 20 + kw + 4];
            }
            #pragma unroll
            for (int nt = 0; nt < 4; nt++) {
                int cb = (wn * 32 + nt * 8 + gid) * 20 + kw;
                uint32_t b0h = Bh[cb], b1h = Bh[cb + 4];
                uint32_t b0l = Bl[cb], b1l = Bl[cb + 4];
                #pragma unroll
                for (int mt = 0; mt < 4; mt++) {
                    mma4(acc[mt][nt], ah[mt], b0h, b1h);
                    mma4(acc[mt][nt], ah[mt], b0l, b1l);
                    mma4(acc[mt][nt], al[mt], b0h, b1h);
                }
            }
        }
        __syncthreads();
    }

    // ---- epilogue ----
    if (mode < 3) {
        const float* bias = (mode == 0) ? bq : (mode == 1) ? bk : bv;
        ushort_t* Dh = (ushort_t*)((mode == 0) ? g_q_hi : (mode == 1) ? g_k_hi : g_v_hi);
        ushort_t* Dl = (ushort_t*)((mode == 0) ? g_q_lo : (mode == 1) ? g_k_lo : g_v_lo);
        #pragma unroll
        for (int mt = 0; mt < 4; mt++) {
            int r = m0 + wm * 64 + mt * 16 + gid;
            int batch = r >> 11, sr = r & (SEQ - 1);
            #pragma unroll
            for (int nt = 0; nt < 4; nt++) {
                int n = n0 + wn * 32 + nt * 8 + 2 * tig;
                float2 bb = *reinterpret_cast<const float2*>(bias + n);
                int head = n >> 6, d = n & 63;
                size_t e0 = ((size_t)(batch * NH + head) * SEQ + sr) * DK + d;
                size_t e1 = e0 + (size_t)8 * DK;
                uint32_t hh, ll;
                split2(acc[mt][nt][0] + bb.x, acc[mt][nt][1] + bb.y, hh, ll);
                *reinterpret_cast<uint32_t*>(Dh + e0) = hh;
                *reinterpret_cast<uint32_t*>(Dl + e0) = ll;
                split2(acc[mt][nt][2] + bb.x, acc[mt][nt][3] + bb.y, hh, ll);
                *reinterpret_cast<uint32_t*>(Dh + e1) = hh;
                *reinterpret_cast<uint32_t*>(Dl + e1) = ll;
            }
        }
    } else {
        #pragma unroll
        for (int mt = 0; mt < 4; mt++) {
            int r = m0 + wm * 64 + mt * 16 + gid;
            #pragma unroll
            for (int nt = 0; nt < 4; nt++) {
                int n = n0 + wn * 32 + nt * 8 + 2 * tig;
                float2 bb = *reinterpret_cast<const float2*>(bo + n);
                float2 h0 = *reinterpret_cast<const float2*>(hres + (size_t)r * DM + n);
                float2 h1 = *reinterpret_cast<const float2*>(hres + (size_t)(r + 8) * DM + n);
                float2 r0 = make_float2(acc[mt][nt][0] + bb.x + h0.x,
                                        acc[mt][nt][1] + bb.y + h0.y);
                float2 r1 = make_float2(acc[mt][nt][2] + bb.x + h1.x,
                                        acc[mt][nt][3] + bb.y + h1.y);
                *reinterpret_cast<float2*>(out + (size_t)r * DM + n) = r0;
                *reinterpret_cast<float2*>(out + (size_t)(r + 8) * DM + n) = r1;
            }
        }
    }
}

// ============================================================
// V transpose: g_v[bh][s][d] -> g_vt[bh][d][s]  (hi and lo)
// ============================================================
__global__ void __launch_bounds__(256) vtrans_kernel()
{
    __shared__ __align__(16) ushort_t tile[64][74];
    const int tid = threadIdx.x;
    const int jt = blockIdx.x, bh = blockIdx.y;

    #pragma unroll
    for (int sel = 0; sel < 2; sel++) {
        const ushort_t* src = (const ushort_t*)(sel ? g_v_lo : g_v_hi)
                              + ((size_t)bh * SEQ + jt * 64) * DK;
        ushort_t* dst = (ushort_t*)(sel ? g_vt_lo : g_vt_hi)
                        + (size_t)bh * DK * SEQ + jt * 64;
        if (sel) __syncthreads();
        #pragma unroll
        for (int it = 0; it < 2; it++) {
            int idx = it * 256 + tid, j = idx >> 3, ch = idx & 7;
            uint4 v = *reinterpret_cast<const uint4*>(src + (size_t)j * DK + ch * 8);
            uint32_t* tw = reinterpret_cast<uint32_t*>(&tile[j][ch * 8]);
            tw[0] = v.x; tw[1] = v.y; tw[2] = v.z; tw[3] = v.w;
        }
        __syncthreads();
        #pragma unroll
        for (int it = 0; it < 2; it++) {
            int idx = it * 256 + tid, d = idx >> 3, ch = idx & 7;
            int jb = ch * 8;
            uint32_t w0 = (uint32_t)tile[jb + 0][d] | ((uint32_t)tile[jb + 1][d] << 16);
            uint32_t w1 = (uint32_t)tile[jb + 2][d] | ((uint32_t)tile[jb + 3][d] << 16);
            uint32_t w2 = (uint32_t)tile[jb + 4][d] | ((uint32_t)tile[jb + 5][d] << 16);
            uint32_t w3 = (uint32_t)tile[jb + 6][d] | ((uint32_t)tile[jb + 7][d] << 16);
            *reinterpret_cast<uint4*>(dst + (size_t)d * SEQ + jb) = make_uint4(w0, w1, w2, w3);
        }
        __syncthreads();
    }
}

// ============================================================
// Flash attention on HMMA: 128 q-rows/CTA, 16 per warp.
// S = Q K^T (split bf16 x3), online softmax in fragments,
// P re-split in regs -> A operand of P V (split x3).
// ============================================================
__global__ void __launch_bounds__(256, 1) attn_hmma()
{
    __shared__ __align__(16) ushort_t Kh[64][72], Kl[64][72];
    __shared__ __align__(16) ushort_t Vh[64][72], Vl[64][72];

    const int tid = threadIdx.x, lane = tid & 31, wid = tid >> 5;
    const int gid = lane >> 2, tig = lane & 3;
    const int qt = blockIdx.x, bh = blockIdx.y;
    const size_t bhQK = (size_t)bh * SEQ * DK;

    // --- preload Q fragments (scaled by 1/sqrt(dk) = 0.125, exact) ---
    uint32_t qh[4][4], ql[4][4];
    {
        const ushort_t* qhp = (const ushort_t*)g_q_hi + bhQK;
        const ushort_t* qlp = (const ushort_t*)g_q_lo + bhQK;
        const int r0 = qt * 128 + wid * 16 + gid;
        #pragma unroll
        for (int ks = 0; ks < 4; ks++) {
            int c = ks * 16 + 2 * tig;
            qh[ks][0] = scale8(*(const uint32_t*)(qhp + (size_t)r0 * DK + c));
            qh[ks][1] = scale8(*(const uint32_t*)(qhp + (size_t)(r0 + 8) * DK + c));
            qh[ks][2] = scale8(*(const uint32_t*)(qhp + (size_t)r0 * DK + c + 8));
            qh[ks][3] = scale8(*(const uint32_t*)(qhp + (size_t)(r0 + 8) * DK + c + 8));
            ql[ks][0] = scale8(*(const uint32_t*)(qlp + (size_t)r0 * DK + c));
            ql[ks][1] = scale8(*(const uint32_t*)(qlp + (size_t)(r0 + 8) * DK + c));
            ql[ks][2] = scale8(*(const uint32_t*)(qlp + (size_t)r0 * DK + c + 8));
            ql[ks][3] = scale8(*(const uint32_t*)(qlp + (size_t)(r0 + 8) * DK + c + 8));
        }
    }

    float o[8][4] = {};
    float m0 = -1e30f, m1 = -1e30f, l0 = 0.f, l1 = 0.f;

    const ushort_t* kh_g = (const ushort_t*)g_k_hi + bhQK;
    const ushort_t* kl_g = (const ushort_t*)g_k_lo + bhQK;
    const ushort_t* vh_g = (const ushort_t*)g_vt_hi + (size_t)bh * DK * SEQ;
    const ushort_t* vl_g = (const ushort_t*)g_vt_lo + (size_t)bh * DK * SEQ;

    for (int jt = 0; jt < SEQ / 64; jt++) {
        const int j0 = jt * 64;
        // ---- load K (hi/lo) and V^T (hi/lo) tiles ----
        #pragma unroll
        for (int it = 0; it < 2; it++) {
            int idx = it * 256 + tid, row = idx >> 3, ch = idx & 7;
            CP16(smem_u32(&Kh[row][ch * 8]), kh_g + (size_t)(j0 + row) * DK + ch * 8);
            CP16(smem_u32(&Kl[row][ch * 8]), kl_g + (size_t)(j0 + row) * DK + ch * 8);
            CP16(smem_u32(&Vh[row][ch * 8]), vh_g + (size_t)row * SEQ + j0 + ch * 8);
            CP16(smem_u32(&Vl[row][ch * 8]), vl_g + (size_t)row * SEQ + j0 + ch * 8);
        }
        CP_COMMIT();
        CP_WAIT0();
        __syncthreads();

        // ---- S = Q K^T ----
        float s[8][4] = {};
        const uint32_t* KhW = reinterpret_cast<const uint32_t*>(Kh);
        const uint32_t* KlW = reinterpret_cast<const uint32_t*>(Kl);
        #pragma unroll
        for (int ks = 0; ks < 4; ks++) {
            #pragma unroll
            for (int nt = 0; nt < 8; nt++) {
                int cb = (nt * 8 + gid) * 36 + ks * 8 + tig;
                uint32_t b0h = KhW[cb], b1h = KhW[cb + 4];
                uint32_t b0l = KlW[cb], b1l = KlW[cb + 4];
                mma4(s[nt], qh[ks], b0h, b1h);
                mma4(s[nt], qh[ks], b0l, b1l);
                mma4(s[nt], ql[ks], b0h, b1h);
            }
        }

        // ---- online softmax (rows gid / gid+8; quad lanes xor 1,2) ----
        float tm0 = -1e30f, tm1 = -1e30f;
        #pragma unroll
        for (int nt = 0; nt < 8; nt++) {
            tm0 = fmaxf(tm0, fmaxf(s[nt][0], s[nt][1]));
            tm1 = fmaxf(tm1, fmaxf(s[nt][2], s[nt][3]));
        }
        tm0 = fmaxf(tm0, __shfl_xor_sync(0xffffffffu, tm0, 1));
        tm0 = fmaxf(tm0, __shfl_xor_sync(0xffffffffu, tm0, 2));
        tm1 = fmaxf(tm1, __shfl_xor_sync(0xffffffffu, tm1, 1));
        tm1 = fmaxf(tm1, __shfl_xor_sync(0xffffffffu, tm1, 2));
        float mn0 = fmaxf(m0, tm0), mn1 = fmaxf(m1, tm1);
        float c0 = __expf(m0 - mn0), c1 = __expf(m1 - mn1);
        m0 = mn0; m1 = mn1;
        float s0 = 0.f, s1 = 0.f;
        #pragma unroll
        for (int nt = 0; nt < 8; nt++) {
            float p0 = __expf(s[nt][0] - m0);
            float p1 = __expf(s[nt][1] - m0);
            float p2 = __expf(s[nt][2] - m1);
            float p3 = __expf(s[nt][3] - m1);
            s[nt][0] = p0; s[nt][1] = p1; s[nt][2] = p2; s[nt][3] = p3;
            s0 += p0 + p1;
            s1 += p2 + p3;
        }
        s0 += __shfl_xor_sync(0xffffffffu, s0, 1);
        s0 += __shfl_xor_sync(0xffffffffu, s0, 2);
        s1 += __shfl_xor_sync(0xffffffffu, s1, 1);
        s1 += __shfl_xor_sync(0xffffffffu, s1, 2);
        l0 = l0 * c0 + s0;
        l1 = l1 * c1 + s1;
        #pragma unroll
        for (int dt = 0; dt < 8; dt++) {
            o[dt][0] *= c0; o[dt][1] *= c0;
            o[dt][2] *= c1; o[dt][3] *= c1;
        }

        // ---- P -> split bf16 A fragments ----
        uint32_t pha[4][4], pla[4][4];
        #pragma unroll
        for (int ks = 0; ks < 4; ks++) {
            split2(s[2*ks][0],   s[2*ks][1],   pha[ks][0], pla[ks][0]);
            split2(s[2*ks][2],   s[2*ks][3],   pha[ks][1], pla[ks][1]);
            split2(s[2*ks+1][0], s[2*ks+1][1], pha[ks][2], pla[ks][2]);
            split2(s[2*ks+1][2], s[2*ks+1][3], pha[ks][3], pla[ks][3]);
        }

        // ---- O += P V ----
        const uint32_t* VhW = reinterpret_cast<const uint32_t*>(Vh);
        const uint32_t* VlW = reinterpret_cast<const uint32_t*>(Vl);
        #pragma unroll
        for (int ks = 0; ks < 4; ks++) {
            #pragma unroll
            for (int dt = 0; dt < 8; dt++) {
                int cb = (dt * 8 + gid) * 36 + ks * 8 + tig;
                uint32_t b0h = VhW[cb], b1h = VhW[cb + 4];
                uint32_t b0l = VlW[cb], b1l = VlW[cb + 4];
                mma4(o[dt], pha[ks], b0h, b1h);
                mma4(o[dt], pha[ks], b0l, b1l);
                mma4(o[dt], pla[ks], b0h, b1h);
            }
        }
        __syncthreads();
    }

    // ---- epilogue: normalize, split, store to g_o hi/lo ----
    const float i0 = 1.0f / l0, i1 = 1.0f / l1;
    const int head = bh & (NH - 1), batch = bh >> 4;
    const int r0 = qt * 128 + wid * 16 + gid;
    ushort_t* Oh = (ushort_t*)g_o_hi;
    ushort_t* Ol = (ushort_t*)g_o_lo;
    size_t mrow0 = (size_t)(batch * SEQ + r0) * DM;
    size_t mrow1 = mrow0 + (size_t)8 * DM;
    #pragma unroll
    for (int dt = 0; dt < 8; dt++) {
        int col = head * 64 + dt * 8 + 2 * tig;
        uint32_t hh, ll;
        split2(o[dt][0] * i0, o[dt][1] * i0, hh, ll);
        *reinterpret_cast<uint32_t*>(Oh + mrow0 + col) = hh;
        *reinterpret_cast<uint32_t*>(Ol + mrow0 + col) = ll;
        split2(o[dt][2] * i1, o[dt][3] * i1, hh, ll);
        *reinterpret_cast<uint32_t*>(Oh + mrow1 + col) = hh;
        *reinterpret_cast<uint32_t*>(Ol + mrow1 + col) = ll;
    }
}

// ============================================================
extern "C" void kernel_launch(void* const* d_in, const int* in_sizes, int n_in,
                              void* d_out, int out_size)
{
    const float* h  = (const float*)d_in[0];
    const float* Wq = (const float*)d_in[1];
    const float* bq = (const float*)d_in[2];
    const float* Wk = (const float*)d_in[3];
    const float* bk = (const float*)d_in[4];
    const float* Wv = (const float*)d_in[5];
    const float* bv = (const float*)d_in[6];
    const float* Wo = (const float*)d_in[7];
    const float* bo = (const float*)d_in[8];
    const float* lw = (const float*)d_in[9];
    const float* lb = (const float*)d_in[10];
    float* out = (float*)d_out;

    cudaFuncSetAttribute(gemm_hmma, cudaFuncAttributeMaxDynamicSharedMemorySize, GEMM_SMEM);

    ln_kernel<<<ROWS, 256>>>(h, lw, lb);
    wconv_kernel<<<dim3(DM, 4), 256>>>(Wq, Wk, Wv, Wo);
    gemm_hmma<<<dim3(DM / 128, ROWS / 128, 3), 256, GEMM_SMEM>>>(0, bq, bk, bv, bo, h, out);
    vtrans_kernel<<<dim3(SEQ / 64, BHCNT), 256>>>();
    attn_hmma<<<dim3(SEQ / 128, BHCNT), 256>>>();
    gemm_hmma<<<dim3(DM / 128, ROWS / 128, 1), 256, GEMM_SMEM>>>(3, bq, bk, bv, bo, h, out);
}

// round 5
// speedup vs baseline: 2.7984x; 1.1297x over previous
#include <cuda_runtime.h>
#include <cuda_bf16.h>
#include <math.h>
#include <stdint.h>

#define DM 1024
#define SEQ 2048
#define BT 2
#define NH 16
#define DK 64
#define ROWS (BT*SEQ)      /* 4096 */
#define BHCNT (BT*NH)      /* 32   */

typedef unsigned short ushort_t;

// -------- scratch (device globals; no runtime allocation) --------
static __device__ __align__(16) __nv_bfloat16 g_hn_hi[(size_t)ROWS * DM];
static __device__ __align__(16) __nv_bfloat16 g_hn_lo[(size_t)ROWS * DM];
static __device__ __align__(16) __nv_bfloat16 g_w_hi[(size_t)4 * DM * DM];
static __device__ __align__(16) __nv_bfloat16 g_w_lo[(size_t)4 * DM * DM];
static __device__ __align__(16) __nv_bfloat16 g_q_hi[(size_t)BHCNT * SEQ * DK];
static __device__ __align__(16) __nv_bfloat16 g_q_lo[(size_t)BHCNT * SEQ * DK];
static __device__ __align__(16) __nv_bfloat16 g_k_hi[(size_t)BHCNT * SEQ * DK];
static __device__ __align__(16) __nv_bfloat16 g_k_lo[(size_t)BHCNT * SEQ * DK];
static __device__ __align__(16) __nv_bfloat16 g_v_hi[(size_t)BHCNT * SEQ * DK];
static __device__ __align__(16) __nv_bfloat16 g_v_lo[(size_t)BHCNT * SEQ * DK];
static __device__ __align__(16) __nv_bfloat16 g_vt_hi[(size_t)BHCNT * DK * SEQ];
static __device__ __align__(16) __nv_bfloat16 g_vt_lo[(size_t)BHCNT * DK * SEQ];
static __device__ __align__(16) __nv_bfloat16 g_o_hi[(size_t)ROWS * DM];
static __device__ __align__(16) __nv_bfloat16 g_o_lo[(size_t)ROWS * DM];

// ============================================================
// helpers
// ============================================================
__device__ __forceinline__ uint32_t smem_u32(const void* p) {
    uint32_t a;
    asm("{ .reg .u64 t; cvta.to.shared.u64 t, %1; cvt.u32.u64 %0, t; }"
        : "=r"(a) : "l"(p));
    return a;
}

#define CP16(dst, src) \
    asm volatile("cp.async.cg.shared.global [%0], [%1], 16;" :: "r"(dst), "l"(src))
#define CP_COMMIT() asm volatile("cp.async.commit_group;" ::: "memory")
#define CP_WAIT0()  asm volatile("cp.async.wait_group 0;" ::: "memory")
#define CP_WAIT1()  asm volatile("cp.async.wait_group 1;" ::: "memory")

// D += A * B  (m16n8k16, bf16 in, fp32 accum)
__device__ __forceinline__ void mma4(float* d, const uint32_t* a,
                                     uint32_t b0, uint32_t b1) {
    asm volatile("mma.sync.aligned.m16n8k16.row.col.f32.bf16.bf16.f32 "
        "{%0,%1,%2,%3}, {%4,%5,%6,%7}, {%8,%9}, {%0,%1,%2,%3};"
        : "+f"(d[0]), "+f"(d[1]), "+f"(d[2]), "+f"(d[3])
        : "r"(a[0]), "r"(a[1]), "r"(a[2]), "r"(a[3]), "r"(b0), "r"(b1));
}

// split two fp32 -> packed bf16x2 hi + packed bf16x2 lo (x in low half)
__device__ __forceinline__ void split2(float x, float y, uint32_t& h, uint32_t& l) {
    __nv_bfloat16 xh = __float2bfloat16_rn(x);
    __nv_bfloat16 yh = __float2bfloat16_rn(y);
    __nv_bfloat16 xl = __float2bfloat16_rn(x - __bfloat162float(xh));
    __nv_bfloat16 yl = __float2bfloat16_rn(y - __bfloat162float(yh));
    __nv_bfloat162 H(xh, yh), L(xl, yl);
    h = *reinterpret_cast<uint32_t*>(&H);
    l = *reinterpret_cast<uint32_t*>(&L);
}

// multiply both bf16 halves by 0.125 (exact: power of two)
__device__ __forceinline__ uint32_t scale8(uint32_t w) {
    __nv_bfloat162 t = *reinterpret_cast<__nv_bfloat162*>(&w);
    float2 f = __bfloat1622float2(t);
    __nv_bfloat162 r = __floats2bfloat162_rn(f.x * 0.125f, f.y * 0.125f);
    return *reinterpret_cast<uint32_t*>(&r);
}

// ============================================================
// LayerNorm -> bf16 hi/lo row-major
// ============================================================
__global__ void __launch_bounds__(256) ln_kernel(const float* __restrict__ h,
                                                 const float* __restrict__ w,
                                                 const float* __restrict__ b)
{
    const int row = blockIdx.x;
    const int t = threadIdx.x;
    const float4* x4 = reinterpret_cast<const float4*>(h) + (size_t)row * (DM / 4);
    float4 v = x4[t];
    float s  = v.x + v.y + v.z + v.w;
    float sq = v.x*v.x + v.y*v.y + v.z*v.z + v.w*v.w;
    #pragma unroll
    for (int o = 16; o > 0; o >>= 1) {
        s  += __shfl_xor_sync(0xffffffffu, s,  o);
        sq += __shfl_xor_sync(0xffffffffu, sq, o);
    }
    __shared__ float sh[16];
    __shared__ float mu_s, rs_s;
    const int wid = t >> 5;
    if ((t & 31) == 0) { sh[wid] = s; sh[8 + wid] = sq; }
    __syncthreads();
    if (t == 0) {
        float S = 0.f, Q = 0.f;
        #pragma unroll
        for (int i = 0; i < 8; i++) { S += sh[i]; Q += sh[8 + i]; }
        float mu  = S * (1.0f / DM);
        float var = Q * (1.0f / DM) - mu * mu;
        mu_s = mu;
        rs_s = rsqrtf(var + 1e-5f);
    }
    __syncthreads();
    const float mu = mu_s, rs = rs_s;
    float4 wv = reinterpret_cast<const float4*>(w)[t];
    float4 bv = reinterpret_cast<const float4*>(b)[t];
    float o0 = (v.x - mu) * rs * wv.x + bv.x;
    float o1 = (v.y - mu) * rs * wv.y + bv.y;
    float o2 = (v.z - mu) * rs * wv.z + bv.z;
    float o3 = (v.w - mu) * rs * wv.w + bv.w;

    uint32_t h01, l01, h23, l23;
    split2(o0, o1, h01, l01);
    split2(o2, o3, h23, l23);
    size_t e = (size_t)row * DM + 4 * t;
    *reinterpret_cast<uint2*>((ushort_t*)g_hn_hi + e) = make_uint2(h01, h23);
    *reinterpret_cast<uint2*>((ushort_t*)g_hn_lo + e) = make_uint2(l01, l23);
}

// ============================================================
// Weight conversion: fp32 [n][k] -> bf16 hi/lo row-major
// ============================================================
__global__ void __launch_bounds__(256) wconv_kernel(
    const float* __restrict__ Wq, const float* __restrict__ Wk,
    const float* __restrict__ Wv, const float* __restrict__ Wo)
{
    const int wsel = blockIdx.y;
    const float* W = (wsel == 0) ? Wq : (wsel == 1) ? Wk : (wsel == 2) ? Wv : Wo;
    const int n = blockIdx.x;
    const int t = threadIdx.x;
    float4 v = *reinterpret_cast<const float4*>(W + (size_t)n * DM + 4 * t);
    uint32_t h01, l01, h23, l23;
    split2(v.x, v.y, h01, l01);
    split2(v.z, v.w, h23, l23);
    size_t e = (size_t)wsel * DM * DM + (size_t)n * DM + 4 * t;
    *reinterpret_cast<uint2*>((ushort_t*)g_w_hi + e) = make_uint2(h01, h23);
    *reinterpret_cast<uint2*>((ushort_t*)g_w_lo + e) = make_uint2(l01, l23);
}

// ============================================================
// HMMA split-bf16 GEMM: C[128x128] = A[128xK] * W[128xK]^T (+bias...)
// 8 warps, warp tile 64x32, BK=32, double-buffered cp.async.
// NOW 2 CTAs/SM (160KB smem, <=128 regs) for latency hiding.
// ============================================================
#define GMAT_W   2560                 /* words per 128x40 bf16 matrix */
#define GSTAGE_W (4 * GMAT_W)         /* Ahi Alo Bhi Blo */
#define GEMM_SMEM (2 * GSTAGE_W * 4)  /* bytes = 80KB */

__global__ void __launch_bounds__(256, 2) gemm_hmma(
    int mode_base,
    const float* __restrict__ bq, const float* __restrict__ bk,
    const float* __restrict__ bv, const float* __restrict__ bo,
    const float* __restrict__ hres, float* __restrict__ out)
{
    extern __shared__ __align__(16) uint32_t gsm[];
    const int tid = threadIdx.x, lane = tid & 31, wid = tid >> 5;
    const int gid = lane >> 2, tig = lane & 3;
    const int wm = wid & 1, wn = wid >> 1;
    const int mode = mode_base + blockIdx.z;
    const int m0 = blockIdx.y * 128, n0 = blockIdx.x * 128;

    const ushort_t* Agh = (const ushort_t*)((mode < 3) ? g_hn_hi : g_o_hi);
    const ushort_t* Agl = (const ushort_t*)((mode < 3) ? g_hn_lo : g_o_lo);
    const int ws = (mode < 3) ? mode : 3;
    const ushort_t* Bgh = (const ushort_t*)g_w_hi + (size_t)ws * DM * DM;
    const ushort_t* Bgl = (const ushort_t*)g_w_lo + (size_t)ws * DM * DM;

    const uint32_t sb = smem_u32(gsm);

    auto load_stage = [&](int s, int i) {
        #pragma unroll
        for (int half = 0; half < 2; half++) {
            int row = (tid >> 2) + 64 * half;
            int ch = tid & 3;
            size_t gA = (size_t)(m0 + row) * DM + i * 32 + ch * 8;
            size_t gB = (size_t)(n0 + row) * DM + i * 32 + ch * 8;
            uint32_t ds = sb + (s * GSTAGE_W + row * 20 + ch * 4) * 4;
            CP16(ds,                Agh + gA);
            CP16(ds + GMAT_W * 4,   Agl + gA);
            CP16(ds + 2*GMAT_W*4,   Bgh + gB);
            CP16(ds + 3*GMAT_W*4,   Bgl + gB);
        }
    };

    float acc[4][4][4] = {};

    load_stage(0, 0);
    CP_COMMIT();

    for (int i = 0; i < DM / 32; i++) {
        if (i + 1 < DM / 32) {
            load_stage((i + 1) & 1, i + 1);
            CP_COMMIT();
            CP_WAIT1();
        } else {
            CP_WAIT0();
        }
        __syncthreads();

        const uint32_t* Wp = gsm + (i & 1) * GSTAGE_W;
        const uint32_t* Ah = Wp;
        const uint32_t* Al = Wp + GMAT_W;
        const uint32_t* Bh = Wp + 2 * GMAT_W;
        const uint32_t* Bl = Wp + 3 * GMAT_W;

        #pragma unroll
        for (int ks = 0; ks < 2; ks++) {
            const int kw = ks * 8 + tig;
            uint32_t ah[4][4], al[4][4];
            #pragma unroll
            for (int mt = 0; mt < 4; mt++) {
                int r = wm * 64 + mt * 16 + gid;
                ah[mt][0] = Ah[r * 20 + kw];
                ah[mt][1] = Ah[(r + 8) * 20 + kw];
                ah[mt][2] = Ah[r * 20 + kw + 4];
                ah[mt][3] = Ah[(r + 8) * 20 + kw + 4];
                al[mt][0] = Al[r * 20 + kw];
                al[mt][1] = Al[(r + 8) * 20 + kw];
                al[mt][2] = Al[r * 20 + kw + 4];
                al[mt][3] = Al[(r + 8) * 20 + kw + 4];
            }
            #pragma unroll
            for (int nt = 0; nt < 4; nt++) {
                int cb = (wn * 32 + nt * 8 + gid) * 20 + kw;
                uint32_t b0h = Bh[cb], b1h = Bh[cb + 4];
                uint32_t b0l = Bl[cb], b1l = Bl[cb + 4];
                #pragma unroll
                for (int mt = 0; mt < 4; mt++) {
                    mma4(acc[mt][nt], ah[mt], b0h, b1h);
                    mma4(acc[mt][nt], ah[mt], b0l, b1l);
                    mma4(acc[mt][nt], al[mt], b0h, b1h);
                }
            }
        }
        __syncthreads();
    }

    // ---- epilogue ----
    if (mode < 3) {
        const float* bias = (mode == 0) ? bq : (mode == 1) ? bk : bv;
        ushort_t* Dh = (ushort_t*)((mode == 0) ? g_q_hi : (mode == 1) ? g_k_hi : g_v_hi);
        ushort_t* Dl = (ushort_t*)((mode == 0) ? g_q_lo : (mode == 1) ? g_k_lo : g_v_lo);
        #pragma unroll
        for (int mt = 0; mt < 4; mt++) {
            int r = m0 + wm * 64 + mt * 16 + gid;
            int batch = r >> 11, sr = r & (SEQ - 1);
            #pragma unroll
            for (int nt = 0; nt < 4; nt++) {
                int n = n0 + wn * 32 + nt * 8 + 2 * tig;
                float2 bb = *reinterpret_cast<const float2*>(bias + n);
                int head = n >> 6, d = n & 63;
                size_t e0 = ((size_t)(batch * NH + head) * SEQ + sr) * DK + d;
                size_t e1 = e0 + (size_t)8 * DK;
                uint32_t hh, ll;
                split2(acc[mt][nt][0] + bb.x, acc[mt][nt][1] + bb.y, hh, ll);
                *reinterpret_cast<uint32_t*>(Dh + e0) = hh;
                *reinterpret_cast<uint32_t*>(Dl + e0) = ll;
                split2(acc[mt][nt][2] + bb.x, acc[mt][nt][3] + bb.y, hh, ll);
                *reinterpret_cast<uint32_t*>(Dh + e1) = hh;
                *reinterpret_cast<uint32_t*>(Dl + e1) = ll;
            }
        }
    } else {
        #pragma unroll
        for (int mt = 0; mt < 4; mt++) {
            int r = m0 + wm * 64 + mt * 16 + gid;
            #pragma unroll
            for (int nt = 0; nt < 4; nt++) {
                int n = n0 + wn * 32 + nt * 8 + 2 * tig;
                float2 bb = *reinterpret_cast<const float2*>(bo + n);
                float2 h0 = *reinterpret_cast<const float2*>(hres + (size_t)r * DM + n);
                float2 h1 = *reinterpret_cast<const float2*>(hres + (size_t)(r + 8) * DM + n);
                float2 r0 = make_float2(acc[mt][nt][0] + bb.x + h0.x,
                                        acc[mt][nt][1] + bb.y + h0.y);
                float2 r1 = make_float2(acc[mt][nt][2] + bb.x + h1.x,
                                        acc[mt][nt][3] + bb.y + h1.y);
                *reinterpret_cast<float2*>(out + (size_t)r * DM + n) = r0;
                *reinterpret_cast<float2*>(out + (size_t)(r + 8) * DM + n) = r1;
            }
        }
    }
}

// ============================================================
// V transpose: g_v[bh][s][d] -> g_vt[bh][d][s]  (hi and lo)
// ============================================================
__global__ void __launch_bounds__(256) vtrans_kernel()
{
    __shared__ __align__(16) ushort_t tile[64][74];
    const int tid = threadIdx.x;
    const int jt = blockIdx.x, bh = blockIdx.y;

    #pragma unroll
    for (int sel = 0; sel < 2; sel++) {
        const ushort_t* src = (const ushort_t*)(sel ? g_v_lo : g_v_hi)
                              + ((size_t)bh * SEQ + jt * 64) * DK;
        ushort_t* dst = (ushort_t*)(sel ? g_vt_lo : g_vt_hi)
                        + (size_t)bh * DK * SEQ + jt * 64;
        if (sel) __syncthreads();
        #pragma unroll
        for (int it = 0; it < 2; it++) {
            int idx = it * 256 + tid, j = idx >> 3, ch = idx & 7;
            uint4 v = *reinterpret_cast<const uint4*>(src + (size_t)j * DK + ch * 8);
            uint32_t* tw = reinterpret_cast<uint32_t*>(&tile[j][ch * 8]);
            tw[0] = v.x; tw[1] = v.y; tw[2] = v.z; tw[3] = v.w;
        }
        __syncthreads();
        #pragma unroll
        for (int it = 0; it < 2; it++) {
            int idx = it * 256 + tid, d = idx >> 3, ch = idx & 7;
            int jb = ch * 8;
            uint32_t w0 = (uint32_t)tile[jb + 0][d] | ((uint32_t)tile[jb + 1][d] << 16);
            uint32_t w1 = (uint32_t)tile[jb + 2][d] | ((uint32_t)tile[jb + 3][d] << 16);
            uint32_t w2 = (uint32_t)tile[jb + 4][d] | ((uint32_t)tile[jb + 5][d] << 16);
            uint32_t w3 = (uint32_t)tile[jb + 6][d] | ((uint32_t)tile[jb + 7][d] << 16);
            *reinterpret_cast<uint4*>(dst + (size_t)d * SEQ + jb) = make_uint4(w0, w1, w2, w3);
        }
        __syncthreads();
    }
}

// ============================================================
// Flash attention on HMMA: 128 q-rows/CTA, 16 per warp.
// Double-buffered K/V tiles (cp.async) to overlap loads with MMA.
// ============================================================
#define AST_U 18432                /* ushorts per stage: 4 x 64 x 72 */
#define ATTN_SMEM (2 * AST_U * 2)  /* bytes = 73728 */

__global__ void __launch_bounds__(256, 1) attn_hmma()
{
    extern __shared__ __align__(16) ushort_t asm_[];

    const int tid = threadIdx.x, lane = tid & 31, wid = tid >> 5;
    const int gid = lane >> 2, tig = lane & 3;
    const int qt = blockIdx.x, bh = blockIdx.y;
    const size_t bhQK = (size_t)bh * SEQ * DK;

    const ushort_t* kh_g = (const ushort_t*)g_k_hi + bhQK;
    const ushort_t* kl_g = (const ushort_t*)g_k_lo + bhQK;
    const ushort_t* vh_g = (const ushort_t*)g_vt_hi + (size_t)bh * DK * SEQ;
    const ushort_t* vl_g = (const ushort_t*)g_vt_lo + (size_t)bh * DK * SEQ;

    auto load_kv = [&](int buf, int jt) {
        const int j0 = jt * 64;
        ushort_t* st = asm_ + buf * AST_U;
        #pragma unroll
        for (int it = 0; it < 2; it++) {
            int idx = it * 256 + tid, row = idx >> 3, ch = idx & 7;
            uint32_t d0 = smem_u32(st + row * 72 + ch * 8);
            CP16(d0,                 kh_g + (size_t)(j0 + row) * DK + ch * 8);
            CP16(d0 + 4608 * 2,      kl_g + (size_t)(j0 + row) * DK + ch * 8);
            CP16(d0 + 2 * 4608 * 2,  vh_g + (size_t)row * SEQ + j0 + ch * 8);
            CP16(d0 + 3 * 4608 * 2,  vl_g + (size_t)row * SEQ + j0 + ch * 8);
        }
    };

    load_kv(0, 0);
    CP_COMMIT();

    // --- preload Q fragments (scaled by 1/sqrt(dk) = 0.125, exact) ---
    uint32_t qh[4][4], ql[4][4];
    {
        const ushort_t* qhp = (const ushort_t*)g_q_hi + bhQK;
        const ushort_t* qlp = (const ushort_t*)g_q_lo + bhQK;
        const int r0 = qt * 128 + wid * 16 + gid;
        #pragma unroll
        for (int ks = 0; ks < 4; ks++) {
            int c = ks * 16 + 2 * tig;
            qh[ks][0] = scale8(*(const uint32_t*)(qhp + (size_t)r0 * DK + c));
            qh[ks][1] = scale8(*(const uint32_t*)(qhp + (size_t)(r0 + 8) * DK + c));
            qh[ks][2] = scale8(*(const uint32_t*)(qhp + (size_t)r0 * DK + c + 8));
            qh[ks][3] = scale8(*(const uint32_t*)(qhp + (size_t)(r0 + 8) * DK + c + 8));
            ql[ks][0] = scale8(*(const uint32_t*)(qlp + (size_t)r0 * DK + c));
            ql[ks][1] = scale8(*(const uint32_t*)(qlp + (size_t)(r0 + 8) * DK + c));
            ql[ks][2] = scale8(*(const uint32_t*)(qlp + (size_t)r0 * DK + c + 8));
            ql[ks][3] = scale8(*(const uint32_t*)(qlp + (size_t)(r0 + 8) * DK + c + 8));
        }
    }

    float o[8][4] = {};
    float m0 = -1e30f, m1 = -1e30f, l0 = 0.f, l1 = 0.f;

    for (int jt = 0; jt < SEQ / 64; jt++) {
        // prefetch next tile into the other buffer, then wait for this one
        if (jt + 1 < SEQ / 64) {
            load_kv((jt + 1) & 1, jt + 1);
            CP_COMMIT();
            CP_WAIT1();
        } else {
            CP_WAIT0();
        }
        __syncthreads();

        const ushort_t* st = asm_ + (jt & 1) * AST_U;
        const uint32_t* KhW = reinterpret_cast<const uint32_t*>(st);
        const uint32_t* KlW = reinterpret_cast<const uint32_t*>(st + 4608);
        const uint32_t* VhW = reinterpret_cast<const uint32_t*>(st + 2 * 4608);
        const uint32_t* VlW = reinterpret_cast<const uint32_t*>(st + 3 * 4608);

        // ---- S = Q K^T ----
        float s[8][4] = {};
        #pragma unroll
        for (int ks = 0; ks < 4; ks++) {
            #pragma unroll
            for (int nt = 0; nt < 8; nt++) {
                int cb = (nt * 8 + gid) * 36 + ks * 8 + tig;
                uint32_t b0h = KhW[cb], b1h = KhW[cb + 4];
                uint32_t b0l = KlW[cb], b1l = KlW[cb + 4];
                mma4(s[nt], qh[ks], b0h, b1h);
                mma4(s[nt], qh[ks], b0l, b1l);
                mma4(s[nt], ql[ks], b0h, b1h);
            }
        }

        // ---- online softmax (rows gid / gid+8; quad lanes xor 1,2) ----
        float tm0 = -1e30f, tm1 = -1e30f;
        #pragma unroll
        for (int nt = 0; nt < 8; nt++) {
            tm0 = fmaxf(tm0, fmaxf(s[nt][0], s[nt][1]));
            tm1 = fmaxf(tm1, fmaxf(s[nt][2], s[nt][3]));
        }
        tm0 = fmaxf(tm0, __shfl_xor_sync(0xffffffffu, tm0, 1));
        tm0 = fmaxf(tm0, __shfl_xor_sync(0xffffffffu, tm0, 2));
        tm1 = fmaxf(tm1, __shfl_xor_sync(0xffffffffu, tm1, 1));
        tm1 = fmaxf(tm1, __shfl_xor_sync(0xffffffffu, tm1, 2));
        float mn0 = fmaxf(m0, tm0), mn1 = fmaxf(m1, tm1);
        float c0 = __expf(m0 - mn0), c1 = __expf(m1 - mn1);
        m0 = mn0; m1 = mn1;
        float s0 = 0.f, s1 = 0.f;
        #pragma unroll
        for (int nt = 0; nt < 8; nt++) {
            float p0 = __expf(s[nt][0] - m0);
            float p1 = __expf(s[nt][1] - m0);
            float p2 = __expf(s[nt][2] - m1);
            float p3 = __expf(s[nt][3] - m1);
            s[nt][0] = p0; s[nt][1] = p1; s[nt][2] = p2; s[nt][3] = p3;
            s0 += p0 + p1;
            s1 += p2 + p3;
        }
        s0 += __shfl_xor_sync(0xffffffffu, s0, 1);
        s0 += __shfl_xor_sync(0xffffffffu, s0, 2);
        s1 += __shfl_xor_sync(0xffffffffu, s1, 1);
        s1 += __shfl_xor_sync(0xffffffffu, s1, 2);
        l0 = l0 * c0 + s0;
        l1 = l1 * c1 + s1;
        #pragma unroll
        for (int dt = 0; dt < 8; dt++) {
            o[dt][0] *= c0; o[dt][1] *= c0;
            o[dt][2] *= c1; o[dt][3] *= c1;
        }

        // ---- P -> split bf16 A fragments ----
        uint32_t pha[4][4], pla[4][4];
        #pragma unroll
        for (int ks = 0; ks < 4; ks++) {
            split2(s[2*ks][0],   s[2*ks][1],   pha[ks][0], pla[ks][0]);
            split2(s[2*ks][2],   s[2*ks][3],   pha[ks][1], pla[ks][1]);
            split2(s[2*ks+1][0], s[2*ks+1][1], pha[ks][2], pla[ks][2]);
            split2(s[2*ks+1][2], s[2*ks+1][3], pha[ks][3], pla[ks][3]);
        }

        // ---- O += P V ----
        #pragma unroll
        for (int ks = 0; ks < 4; ks++) {
            #pragma unroll
            for (int dt = 0; dt < 8; dt++) {
                int cb = (dt * 8 + gid) * 36 + ks * 8 + tig;
                uint32_t b0h = VhW[cb], b1h = VhW[cb + 4];
                uint32_t b0l = VlW[cb], b1l = VlW[cb + 4];
                mma4(o[dt], pha[ks], b0h, b1h);
                mma4(o[dt], pha[ks], b0l, b1l);
                mma4(o[dt], pla[ks], b0h, b1h);
            }
        }
        __syncthreads();
    }

    // ---- epilogue: normalize, split, store to g_o hi/lo ----
    const float i0 = 1.0f / l0, i1 = 1.0f / l1;
    const int head = bh & (NH - 1), batch = bh >> 4;
    const int r0 = qt * 128 + wid * 16 + gid;
    ushort_t* Oh = (ushort_t*)g_o_hi;
    ushort_t* Ol = (ushort_t*)g_o_lo;
    size_t mrow0 = (size_t)(batch * SEQ + r0) * DM;
    size_t mrow1 = mrow0 + (size_t)8 * DM;
    #pragma unroll
    for (int dt = 0; dt < 8; dt++) {
        int col = head * 64 + dt * 8 + 2 * tig;
        uint32_t hh, ll;
        split2(o[dt][0] * i0, o[dt][1] * i0, hh, ll);
        *reinterpret_cast<uint32_t*>(Oh + mrow0 + col) = hh;
        *reinterpret_cast<uint32_t*>(Ol + mrow0 + col) = ll;
        split2(o[dt][2] * i1, o[dt][3] * i1, hh, ll);
        *reinterpret_cast<uint32_t*>(Oh + mrow1 + col) = hh;
        *reinterpret_cast<uint32_t*>(Ol + mrow1 + col) = ll;
    }
}

// ============================================================
extern "C" void kernel_launch(void* const* d_in, const int* in_sizes, int n_in,
                              void* d_out, int out_size)
{
    const float* h  = (const float*)d_in[0];
    const float* Wq = (const float*)d_in[1];
    const float* bq = (const float*)d_in[2];
    const float* Wk = (const float*)d_in[3];
    const float* bk = (const float*)d_in[4];
    const float* Wv = (const float*)d_in[5];
    const float* bv = (const float*)d_in[6];
    const float* Wo = (const float*)d_in[7];
    const float* bo = (const float*)d_in[8];
    const float* lw = (const float*)d_in[9];
    const float* lb = (const float*)d_in[10];
    float* out = (float*)d_out;

    cudaFuncSetAttribute(gemm_hmma, cudaFuncAttributeMaxDynamicSharedMemorySize, GEMM_SMEM);
    cudaFuncSetAttribute(attn_hmma, cudaFuncAttributeMaxDynamicSharedMemorySize, ATTN_SMEM);

    ln_kernel<<<ROWS, 256>>>(h, lw, lb);
    wconv_kernel<<<dim3(DM, 4), 256>>>(Wq, Wk, Wv, Wo);
    gemm_hmma<<<dim3(DM / 128, ROWS / 128, 3), 256, GEMM_SMEM>>>(0, bq, bk, bv, bo, h, out);
    vtrans_kernel<<<dim3(SEQ / 64, BHCNT), 256>>>();
    attn_hmma<<<dim3(SEQ / 128, BHCNT), 256, ATTN_SMEM>>>();
    gemm_hmma<<<dim3(DM / 128, ROWS / 128, 1), 256, GEMM_SMEM>>>(3, bq, bk, bv, bo, h, out);
}